// round 12
// baseline (speedup 1.0000x reference)
#include <cuda_runtime.h>
#include <math.h>

// Problem constants
#define BB 2
#define SS 1024
#define HID 2048
#define NH 32
#define NKV 8
#define HD 64
#define GROUP 4

#define OUT_ELEMS   (BB * SS * HID)             // 4,194,304
#define ATTN_ELEMS  ((size_t)BB * NH * SS * SS) // 67,108,864
#define NROWS       (BB * NH * SS)              // 65,536 attn rows

// Scratch (device globals: no runtime allocation allowed)
__device__ float g_q[(size_t)BB * NH * SS * HD];
__device__ float g_k[(size_t)BB * NKV * SS * HD];
__device__ float g_v[(size_t)BB * NKV * SS * HD];
__device__ float g_ctx[(size_t)BB * SS * NH * HD];
__device__ float g_inv[NROWS];
__device__ float g_attn_fallback[ATTN_ELEMS];

// ---------------------------------------------------------------------------
// TF32 helpers
// ---------------------------------------------------------------------------
__device__ __forceinline__ unsigned f2tf(float f) {
    unsigned u;
    asm("cvt.rna.tf32.f32 %0, %1;" : "=r"(u) : "f"(f));
    return u;
}

__device__ __forceinline__ void mma_tf32(float c[4],
                                         unsigned a0, unsigned a1, unsigned a2, unsigned a3,
                                         unsigned b0, unsigned b1)
{
    asm volatile(
        "mma.sync.aligned.m16n8k8.row.col.f32.tf32.tf32.f32 "
        "{%0,%1,%2,%3},{%4,%5,%6,%7},{%8,%9},{%0,%1,%2,%3};"
        : "+f"(c[0]), "+f"(c[1]), "+f"(c[2]), "+f"(c[3])
        : "r"(a0), "r"(a1), "r"(a2), "r"(a3), "r"(b0), "r"(b1));
}

__device__ __forceinline__ void cpa16(void* s, const void* g) {
    unsigned sa = (unsigned)__cvta_generic_to_shared(s);
    asm volatile("cp.async.cg.shared.global [%0], [%1], 16;" :: "r"(sa), "l"(g));
}

// ---------------------------------------------------------------------------
// GEMM mainloop: 128x128 tile, BK=16, 3-stage cp.async ring (2-tile lookahead).
// ---------------------------------------------------------------------------
#define AST 20
#define BST 136

__device__ __forceinline__ void gemm_mainloop(
    const float* __restrict__ Ab, const float* __restrict__ Wb,
    int N, int K, float acc[4][4][4], float* As, float* Bs)
{
    const int tid = threadIdx.x;
    const int warp = tid >> 5, lane = tid & 31;
    const int g = lane >> 2, t = lane & 3;
    const int wm = warp >> 2, wn = warp & 3;
    const int arow = tid >> 2, ac4 = (tid & 3) * 4;
    const int brow = tid >> 5, bn4 = (tid & 31) * 4;

    const int ntiles = K / 16;

#pragma unroll
    for (int s = 0; s < 2; s++) {
        if (s < ntiles) {
            const int k0 = s * 16;
            float* An = As + s * 128 * AST;
            float* Bn = Bs + s * 16 * BST;
            cpa16(&An[arow * AST + ac4],        Ab + (size_t)arow * K + k0 + ac4);
            cpa16(&An[(arow + 64) * AST + ac4], Ab + (size_t)(arow + 64) * K + k0 + ac4);
            cpa16(&Bn[brow * BST + bn4],        Wb + (size_t)(k0 + brow) * N + bn4);
            cpa16(&Bn[(brow + 8) * BST + bn4],  Wb + (size_t)(k0 + brow + 8) * N + bn4);
            asm volatile("cp.async.commit_group;");
        }
    }

    for (int i = 0; i < ntiles; i++) {
        if (i + 2 < ntiles) {
            const int k0 = (i + 2) * 16;
            float* An = As + ((i + 2) % 3) * 128 * AST;
            float* Bn = Bs + ((i + 2) % 3) * 16 * BST;
            cpa16(&An[arow * AST + ac4],        Ab + (size_t)arow * K + k0 + ac4);
            cpa16(&An[(arow + 64) * AST + ac4], Ab + (size_t)(arow + 64) * K + k0 + ac4);
            cpa16(&Bn[brow * BST + bn4],        Wb + (size_t)(k0 + brow) * N + bn4);
            cpa16(&Bn[(brow + 8) * BST + bn4],  Wb + (size_t)(k0 + brow + 8) * N + bn4);
            asm volatile("cp.async.commit_group;");
            asm volatile("cp.async.wait_group 2;");
        } else if (i + 1 < ntiles) {
            asm volatile("cp.async.wait_group 1;");
        } else {
            asm volatile("cp.async.wait_group 0;");
        }
        __syncthreads();

        const float* Ac = As + (i % 3) * 128 * AST;
        const float* Bc = Bs + (i % 3) * 16 * BST;

#pragma unroll
        for (int kb = 0; kb < 16; kb += 8) {
            unsigned a[4][4], b[4][2];
#pragma unroll
            for (int mt = 0; mt < 4; mt++) {
                int rb = wm * 64 + mt * 16;
                a[mt][0] = f2tf(Ac[(rb + g) * AST + kb + t]);
                a[mt][1] = f2tf(Ac[(rb + g + 8) * AST + kb + t]);
                a[mt][2] = f2tf(Ac[(rb + g) * AST + kb + t + 4]);
                a[mt][3] = f2tf(Ac[(rb + g + 8) * AST + kb + t + 4]);
            }
#pragma unroll
            for (int nt = 0; nt < 4; nt++) {
                int cb = wn * 32 + nt * 8;
                b[nt][0] = f2tf(Bc[(kb + t) * BST + cb + g]);
                b[nt][1] = f2tf(Bc[(kb + t + 4) * BST + cb + g]);
            }
#pragma unroll
            for (int mt = 0; mt < 4; mt++)
#pragma unroll
                for (int nt = 0; nt < 4; nt++)
                    mma_tf32(acc[mt][nt], a[mt][0], a[mt][1], a[mt][2], a[mt][3],
                             b[nt][0], b[nt][1]);
        }
        __syncthreads();
    }
}

// ---------------------------------------------------------------------------
// Fused QKV projection: grid (24, 16). bn<16 -> Q, bn<20 -> K, else V.
// ---------------------------------------------------------------------------
__global__ __launch_bounds__(256, 2)
void qkv_kernel(const float* __restrict__ hidden,
                const float* __restrict__ wq, const float* __restrict__ wk,
                const float* __restrict__ wv,
                float* __restrict__ qo, float* __restrict__ ko,
                float* __restrict__ vo)
{
    __shared__ float As[3 * 128 * AST];
    __shared__ float Bs[3 * 16 * BST];

    const int bn = blockIdx.x, bm = blockIdx.y;
    const float* W; float* C; int N, nh, bl;
    if (bn < 16)      { W = wq; C = qo; N = 2048; nh = NH;  bl = bn; }
    else if (bn < 20) { W = wk; C = ko; N = 512;  nh = NKV; bl = bn - 16; }
    else              { W = wv; C = vo; N = 512;  nh = NKV; bl = bn - 20; }

    const float* Ab = hidden + (size_t)bm * 128 * 2048;
    const float* Wb = W + bl * 128;

    float acc[4][4][4];
#pragma unroll
    for (int i = 0; i < 4; i++)
#pragma unroll
        for (int j = 0; j < 4; j++)
#pragma unroll
            for (int r = 0; r < 4; r++) acc[i][j][r] = 0.f;

    gemm_mainloop(Ab, Wb, N, 2048, acc, As, Bs);

    const int tid = threadIdx.x;
    const int warp = tid >> 5, lane = tid & 31;
    const int g = lane >> 2, t = lane & 3;
    const int wm = warp >> 2, wn = warp & 3;

#pragma unroll
    for (int mt = 0; mt < 4; mt++)
#pragma unroll
        for (int nt = 0; nt < 4; nt++)
#pragma unroll
            for (int ri = 0; ri < 4; ri++) {
                int r = wm * 64 + mt * 16 + g + ((ri >= 2) ? 8 : 0);
                int c = wn * 32 + nt * 8 + 2 * t + (ri & 1);
                int m = bm * 128 + r, n = bl * 128 + c;
                int b_ = m >> 10, s = m & 1023;
                int head = n >> 6, dd = n & 63;
                C[(((size_t)b_ * nh + head) * SS + s) * HD + dd] = acc[mt][nt][ri];
            }
}

// ---------------------------------------------------------------------------
// Plain GEMM (out projection): C[m*N+n] = A @ W.
// ---------------------------------------------------------------------------
__global__ __launch_bounds__(256, 2)
void gemm_kernel(const float* __restrict__ A, const float* __restrict__ W,
                 float* __restrict__ C, int M, int N, int K)
{
    __shared__ float As[3 * 128 * AST];
    __shared__ float Bs[3 * 16 * BST];

    const int bn = blockIdx.x, bm = blockIdx.y;
    const float* Ab = A + (size_t)bm * 128 * K;
    const float* Wb = W + bn * 128;

    float acc[4][4][4];
#pragma unroll
    for (int i = 0; i < 4; i++)
#pragma unroll
        for (int j = 0; j < 4; j++)
#pragma unroll
            for (int r = 0; r < 4; r++) acc[i][j][r] = 0.f;

    gemm_mainloop(Ab, Wb, N, K, acc, As, Bs);

    const int tid = threadIdx.x;
    const int warp = tid >> 5, lane = tid & 31;
    const int g = lane >> 2, t = lane & 3;
    const int wm = warp >> 2, wn = warp & 3;

#pragma unroll
    for (int mt = 0; mt < 4; mt++)
#pragma unroll
        for (int nt = 0; nt < 4; nt++)
#pragma unroll
            for (int ri = 0; ri < 4; ri++) {
                int r = wm * 64 + mt * 16 + g + ((ri >= 2) ? 8 : 0);
                int c = wn * 32 + nt * 8 + 2 * t + (ri & 1);
                int m = bm * 128 + r, n = bn * 128 + c;
                C[(size_t)m * N + n] = acc[mt][nt][ri];
            }
}

// ---------------------------------------------------------------------------
// RoPE, fused q+k: rows [0, NROWSQ) -> q, rest -> k.
// ---------------------------------------------------------------------------
#define NROWSQ (BB * NH * SS)
#define NROWSK (BB * NKV * SS)

__global__ void rope_kernel(float* __restrict__ qb, float* __restrict__ kb,
                            const float* __restrict__ cosb,
                            const float* __restrict__ sinb)
{
    int idx = blockIdx.x * blockDim.x + threadIdx.x;
    int row = idx >> 5;
    int d = idx & 31;
    float* buf; int r;
    if (row < NROWSQ) { buf = qb; r = row; }
    else              { buf = kb; r = row - NROWSQ; }
    int s = r & (SS - 1);
    float x1 = buf[(size_t)r * HD + d];
    float x2 = buf[(size_t)r * HD + d + 32];
    float c1 = cosb[s * HD + d],      s1 = sinb[s * HD + d];
    float c2 = cosb[s * HD + d + 32], s2 = sinb[s * HD + d + 32];
    buf[(size_t)r * HD + d]      = x1 * c1 - x2 * s1;
    buf[(size_t)r * HD + d + 32] = x2 * c2 + x1 * s2;
}

// ---------------------------------------------------------------------------
// Sumpass: per (z, 64-row q strip), recompute S = Q.K^T over all causal
// k-tiles (K cp.async double-buffered), e = exp(S/8) masked, reduce to
// inv = 1/rowsum. No gmem writes except inv. ~53 KB smem -> 4 CTAs/SM.
// ---------------------------------------------------------------------------
#define SPQ 68
#define SPK 68
#define SP_SMEM ((64 * SPQ + 2 * 64 * SPK + 256) * 4)

__global__ __launch_bounds__(256)
void sumpass_kernel(const float* __restrict__ q, const float* __restrict__ k,
                    const float* __restrict__ mask, float* __restrict__ inv)
{
    extern __shared__ float sm[];
    unsigned* Qs  = (unsigned*)sm;           // 64 x SPQ (tf32)
    float*    Ksm = sm + 64 * SPQ;           // 2 x 64 x SPK
    float*    red = Ksm + 2 * 64 * SPK;      // 256

    const int qt = 15 - blockIdx.x;          // heavy strips first
    const int z  = blockIdx.y;
    const int b = z >> 5, h = z & 31, kvh = h >> 2;
    const int nkt = qt + 1;

    const int tid = threadIdx.x;
    const int warp = tid >> 5, lane = tid & 31;
    const int g = lane >> 2, t = lane & 3;
    const int wm = warp >> 2, wn = warp & 3;

    const float* Qg = q + ((size_t)z * SS + qt * 64) * HD;
    const float* Kg = k + (size_t)(b * NKV + kvh) * SS * HD;
    const float* mrow = mask + (size_t)b * SS;

    // Q -> tf32 smem
#pragma unroll
    for (int l = 0; l < 4; l++) {
        int idx = tid + l * 256;
        int row = idx >> 4, c4 = (idx & 15) * 4;
        float4 qv = *(const float4*)(Qg + (size_t)row * HD + c4);
        Qs[row * SPQ + c4 + 0] = f2tf(qv.x);
        Qs[row * SPQ + c4 + 1] = f2tf(qv.y);
        Qs[row * SPQ + c4 + 2] = f2tf(qv.z);
        Qs[row * SPQ + c4 + 3] = f2tf(qv.w);
    }

    // prologue: K tile 0
    {
#pragma unroll
        for (int l = 0; l < 4; l++) {
            int i4 = tid + l * 256;
            int row = i4 >> 4, c4 = (i4 & 15) * 4;
            cpa16(&Ksm[row * SPK + c4], Kg + (size_t)row * HD + c4);
        }
        asm volatile("cp.async.commit_group;");
    }

    float rs[4] = {0.f, 0.f, 0.f, 0.f};

    for (int kt = 0; kt < nkt; kt++) {
        if (kt + 1 < nkt) {
            float* Kn = Ksm + ((kt + 1) & 1) * 64 * SPK;
            const float* Kgs = Kg + (size_t)(kt + 1) * 64 * HD;
#pragma unroll
            for (int l = 0; l < 4; l++) {
                int i4 = tid + l * 256;
                int row = i4 >> 4, c4 = (i4 & 15) * 4;
                cpa16(&Kn[row * SPK + c4], Kgs + (size_t)row * HD + c4);
            }
            asm volatile("cp.async.commit_group;");
            asm volatile("cp.async.wait_group 1;");
        } else {
            asm volatile("cp.async.wait_group 0;");
        }
        __syncthreads();

        const float* Kc = Ksm + (kt & 1) * 64 * SPK;

        float accs[2][2][4];
#pragma unroll
        for (int i = 0; i < 2; i++)
#pragma unroll
            for (int j = 0; j < 2; j++)
#pragma unroll
                for (int r = 0; r < 4; r++) accs[i][j][r] = 0.f;

#pragma unroll
        for (int kb = 0; kb < 64; kb += 8) {
            unsigned a[2][4], bf[2][2];
#pragma unroll
            for (int mt = 0; mt < 2; mt++) {
                int rb = wm * 32 + mt * 16;
                a[mt][0] = Qs[(rb + g) * SPQ + kb + t];
                a[mt][1] = Qs[(rb + g + 8) * SPQ + kb + t];
                a[mt][2] = Qs[(rb + g) * SPQ + kb + t + 4];
                a[mt][3] = Qs[(rb + g + 8) * SPQ + kb + t + 4];
            }
#pragma unroll
            for (int nt = 0; nt < 2; nt++) {
                int cb = wn * 16 + nt * 8;
                bf[nt][0] = f2tf(Kc[(cb + g) * SPK + kb + t]);
                bf[nt][1] = f2tf(Kc[(cb + g) * SPK + kb + t + 4]);
            }
#pragma unroll
            for (int mt = 0; mt < 2; mt++)
#pragma unroll
                for (int nt = 0; nt < 2; nt++)
                    mma_tf32(accs[mt][nt], a[mt][0], a[mt][1], a[mt][2], a[mt][3],
                             bf[nt][0], bf[nt][1]);
        }

#pragma unroll
        for (int mt = 0; mt < 2; mt++)
#pragma unroll
            for (int nt = 0; nt < 2; nt++)
#pragma unroll
                for (int ri = 0; ri < 4; ri++) {
                    int r = wm * 32 + mt * 16 + g + ((ri >= 2) ? 8 : 0);
                    int c = wn * 16 + nt * 8 + 2 * t + (ri & 1);
                    int qg = qt * 64 + r, kg = kt * 64 + c;
                    bool ok = (kg <= qg) && (mrow[kg] == 1.0f);
                    if (ok) rs[mt * 2 + (ri >> 1)] += __expf(accs[mt][nt][ri] * 0.125f);
                }
        __syncthreads();
    }

    // reduce: t-lanes, then across the 4 n-warps
#pragma unroll
    for (int mt = 0; mt < 2; mt++)
#pragma unroll
        for (int hi = 0; hi < 2; hi++) {
            float vv = rs[mt * 2 + hi];
            vv += __shfl_xor_sync(0xffffffffu, vv, 1);
            vv += __shfl_xor_sync(0xffffffffu, vv, 2);
            if (t == 0)
                red[(wm * 32 + mt * 16 + hi * 8 + g) * 4 + wn] = vv;
        }
    __syncthreads();
    if (tid < 64) {
        float s = red[tid * 4] + red[tid * 4 + 1] + red[tid * 4 + 2] + red[tid * 4 + 3];
        inv[(size_t)z * SS + qt * 64 + tid] = 1.0f / s;
    }
}

// ---------------------------------------------------------------------------
// Scores: writes FINAL normalized attention p = exp(S/8)*inv (masked -> 0).
// e staged in dead Ks smem; coalesced float4 stores scaled by inv.
// ---------------------------------------------------------------------------
#define QST 68

__global__ __launch_bounds__(256)
void scores_kernel(const float* __restrict__ q, const float* __restrict__ k,
                   const float* __restrict__ mask, const float* __restrict__ inv,
                   float* __restrict__ attn)
{
    const int kt = blockIdx.x, qt = blockIdx.y, z = blockIdx.z;
    const int b = z >> 5, h = z & 31, kvh = h >> 2;
    const int tid = threadIdx.x;
    float* outp = attn + ((size_t)z * SS + qt * 64) * SS + kt * 64;

    if (kt > qt) { // fully masked tile
        float4 zero = make_float4(0.f, 0.f, 0.f, 0.f);
#pragma unroll
        for (int i = 0; i < 4; i++) {
            int idx = tid + i * 256;
            int r = idx >> 4, c = (idx & 15) * 4;
            *(float4*)(outp + (size_t)r * SS + c) = zero;
        }
        return;
    }

    const float* Q  = q + (size_t)z * SS * HD + qt * 64 * HD;
    const float* Kp = k + ((size_t)(b * NKV + kvh) * SS + kt * 64) * HD;

    __shared__ unsigned Qs[64 * QST];
    __shared__ unsigned Ks[64 * QST];
    __shared__ float invs[64];

    if (tid < 64) invs[tid] = inv[(size_t)z * SS + qt * 64 + tid];

#pragma unroll
    for (int l = 0; l < 4; l++) {
        int idx = tid + l * 256;
        int row = idx >> 4, c4 = (idx & 15) * 4;
        float4 qv = *(const float4*)(Q + (size_t)row * HD + c4);
        *(uint4*)&Qs[row * QST + c4] =
            make_uint4(f2tf(qv.x), f2tf(qv.y), f2tf(qv.z), f2tf(qv.w));
        float4 kv = *(const float4*)(Kp + (size_t)row * HD + c4);
        *(uint4*)&Ks[row * QST + c4] =
            make_uint4(f2tf(kv.x), f2tf(kv.y), f2tf(kv.z), f2tf(kv.w));
    }
    __syncthreads();

    const int warp = tid >> 5, lane = tid & 31;
    const int g = lane >> 2, t = lane & 3;
    const int wm = warp >> 2, wn = warp & 3;

    float acc[2][2][4];
#pragma unroll
    for (int i = 0; i < 2; i++)
#pragma unroll
        for (int j = 0; j < 2; j++)
#pragma unroll
            for (int r = 0; r < 4; r++) acc[i][j][r] = 0.f;

#pragma unroll
    for (int kb = 0; kb < 64; kb += 8) {
        unsigned a[2][4], bf[2][2];
#pragma unroll
        for (int mt = 0; mt < 2; mt++) {
            int rb = wm * 32 + mt * 16;
            a[mt][0] = Qs[(rb + g) * QST + kb + t];
            a[mt][1] = Qs[(rb + g + 8) * QST + kb + t];
            a[mt][2] = Qs[(rb + g) * QST + kb + t + 4];
            a[mt][3] = Qs[(rb + g + 8) * QST + kb + t + 4];
        }
#pragma unroll
        for (int nt = 0; nt < 2; nt++) {
            int cb = wn * 16 + nt * 8;
            bf[nt][0] = Ks[(cb + g) * QST + kb + t];
            bf[nt][1] = Ks[(cb + g) * QST + kb + t + 4];
        }
#pragma unroll
        for (int mt = 0; mt < 2; mt++)
#pragma unroll
            for (int nt = 0; nt < 2; nt++)
                mma_tf32(acc[mt][nt], a[mt][0], a[mt][1], a[mt][2], a[mt][3],
                         bf[nt][0], bf[nt][1]);
    }
    __syncthreads();                 // all warps done reading Qs/Ks

    // ---- stage raw e into the dead Ks buffer ----
    float* Es = (float*)Ks;
#pragma unroll
    for (int mt = 0; mt < 2; mt++)
#pragma unroll
        for (int nt = 0; nt < 2; nt++)
#pragma unroll
            for (int ri = 0; ri < 4; ri++) {
                int r = wm * 32 + mt * 16 + g + ((ri >= 2) ? 8 : 0);
                int c = wn * 16 + nt * 8 + 2 * t + (ri & 1);
                int qg = qt * 64 + r, kg = kt * 64 + c;
                bool ok = (kg <= qg) && (mask[b * SS + kg] == 1.0f);
                Es[r * QST + c] = ok ? __expf(acc[mt][nt][ri] * 0.125f) : 0.f;
            }
    __syncthreads();

    // ---- coalesced float4 store of NORMALIZED p (4 threads/row) ----
    {
        const int srow = tid >> 2, q4 = tid & 3;
        const float iv = invs[srow];
        const float* src = Es + srow * QST;
        float* dst = outp + (size_t)srow * SS;
#pragma unroll
        for (int p = 0; p < 4; p++) {
            int ch = q4 + p * 4;
            float4 e4 = *(const float4*)&src[ch * 4];
            e4.x *= iv; e4.y *= iv; e4.z *= iv; e4.w *= iv;
            *(float4*)(dst + ch * 4) = e4;
        }
    }
}

// ---------------------------------------------------------------------------
// ctx: reads NORMALIZED p (cp.async double-buffered) and V; ctx = P @ V.
// No attn writes, no inv. cvt.rna fragments (accuracy path).
// ---------------------------------------------------------------------------
#define PST3 68
#define VST3 72
#define CTX_SMEM ((2 * 64 * PST3 + 2 * 64 * VST3) * 4)

__global__ __launch_bounds__(256)
void ctx_kernel(const float* __restrict__ attn, const float* __restrict__ v,
                float* __restrict__ ctx)
{
    extern __shared__ float sm[];
    float* Psm  = sm;                       // 2 x 64 x PST3
    float* Vsm  = sm + 2 * 64 * PST3;       // 2 x 64 x VST3

    const int qt = 15 - blockIdx.x;         // heavy blocks first
    const int z  = blockIdx.y;
    const int b = z >> 5, h = z & 31, kvh = h >> 2;
    const int tid = threadIdx.x;
    const int warp = tid >> 5, lane = tid & 31;
    const int g = lane >> 2, t = lane & 3;
    const int wm = warp >> 2, wn = warp & 3;

    const float* P = attn + ((size_t)z * SS + qt * 64) * SS;
    const float* V = v + (size_t)(b * NKV + kvh) * SS * HD;
    const int nkt = qt + 1;

    // prologue: tile 0
    {
#pragma unroll
        for (int l = 0; l < 4; l++) {
            int i4 = tid + l * 256;
            int row = i4 >> 4, c4 = (i4 & 15) * 4;
            cpa16(&Psm[row * PST3 + c4], P + (size_t)row * SS + c4);
            cpa16(&Vsm[row * VST3 + c4], V + (size_t)row * HD + c4);
        }
        asm volatile("cp.async.commit_group;");
    }

    float acc[2][2][4];
#pragma unroll
    for (int i = 0; i < 2; i++)
#pragma unroll
        for (int j = 0; j < 2; j++)
#pragma unroll
            for (int r = 0; r < 4; r++) acc[i][j][r] = 0.f;

    for (int kt = 0; kt < nkt; kt++) {
        if (kt + 1 < nkt) {
            float* Pn = Psm + ((kt + 1) & 1) * 64 * PST3;
            float* Vn = Vsm + ((kt + 1) & 1) * 64 * VST3;
            const float* Pg = P + (size_t)(kt + 1) * 64;
            const float* Vg = V + (size_t)(kt + 1) * 64 * HD;
#pragma unroll
            for (int l = 0; l < 4; l++) {
                int i4 = tid + l * 256;
                int row = i4 >> 4, c4 = (i4 & 15) * 4;
                cpa16(&Pn[row * PST3 + c4], Pg + (size_t)row * SS + c4);
                cpa16(&Vn[row * VST3 + c4], Vg + (size_t)row * HD + c4);
            }
            asm volatile("cp.async.commit_group;");
            asm volatile("cp.async.wait_group 1;");
        } else {
            asm volatile("cp.async.wait_group 0;");
        }
        __syncthreads();

        const float* Pc = Psm + (kt & 1) * 64 * PST3;
        const float* Vc = Vsm + (kt & 1) * 64 * VST3;

#pragma unroll
        for (int kb = 0; kb < 64; kb += 8) {
            unsigned a[2][4], bf[2][2];
#pragma unroll
            for (int mt = 0; mt < 2; mt++) {
                int rb = wm * 32 + mt * 16;
                a[mt][0] = f2tf(Pc[(rb + g) * PST3 + kb + t]);
                a[mt][1] = f2tf(Pc[(rb + g + 8) * PST3 + kb + t]);
                a[mt][2] = f2tf(Pc[(rb + g) * PST3 + kb + t + 4]);
                a[mt][3] = f2tf(Pc[(rb + g + 8) * PST3 + kb + t + 4]);
            }
#pragma unroll
            for (int nt = 0; nt < 2; nt++) {
                int cb = wn * 16 + nt * 8;
                bf[nt][0] = f2tf(Vc[(kb + t) * VST3 + cb + g]);
                bf[nt][1] = f2tf(Vc[(kb + t + 4) * VST3 + cb + g]);
            }
#pragma unroll
            for (int mt = 0; mt < 2; mt++)
#pragma unroll
                for (int nt = 0; nt < 2; nt++)
                    mma_tf32(acc[mt][nt], a[mt][0], a[mt][1], a[mt][2], a[mt][3],
                             bf[nt][0], bf[nt][1]);
        }
        __syncthreads();
    }

#pragma unroll
    for (int mt = 0; mt < 2; mt++)
#pragma unroll
        for (int nt = 0; nt < 2; nt++)
#pragma unroll
            for (int ri = 0; ri < 4; ri++) {
                int r = wm * 32 + mt * 16 + g + ((ri >= 2) ? 8 : 0);
                int c = wn * 16 + nt * 8 + 2 * t + (ri & 1);
                int qg = qt * 64 + r;
                ctx[((size_t)b * SS + qg) * HID + h * HD + c] = acc[mt][nt][ri];
            }
}

// ---------------------------------------------------------------------------
extern "C" void kernel_launch(void* const* d_in, const int* in_sizes, int n_in,
                              void* d_out, int out_size)
{
    const float* hidden = (const float*)d_in[0];
    const float* mask   = (const float*)d_in[1];
    const float* cosb   = (const float*)d_in[2];
    const float* sinb   = (const float*)d_in[3];
    const float* wq     = (const float*)d_in[4];
    const float* wk     = (const float*)d_in[5];
    const float* wv     = (const float*)d_in[6];
    const float* wo     = (const float*)d_in[7];

    float* outp = (float*)d_out;

    float *qp, *kp, *vp, *cp, *ip;
    cudaGetSymbolAddress((void**)&qp, g_q);
    cudaGetSymbolAddress((void**)&kp, g_k);
    cudaGetSymbolAddress((void**)&vp, g_v);
    cudaGetSymbolAddress((void**)&cp, g_ctx);
    cudaGetSymbolAddress((void**)&ip, g_inv);

    float* attnp;
    if ((size_t)out_size >= OUT_ELEMS + ATTN_ELEMS) {
        attnp = outp + OUT_ELEMS;
    } else {
        cudaGetSymbolAddress((void**)&attnp, g_attn_fallback);
    }

    cudaFuncSetAttribute(sumpass_kernel,
                         cudaFuncAttributeMaxDynamicSharedMemorySize, SP_SMEM);
    cudaFuncSetAttribute(ctx_kernel,
                         cudaFuncAttributeMaxDynamicSharedMemorySize, CTX_SMEM);

    // 1) fused QKV projection (3-stage cp.async pipelined tf32)
    qkv_kernel<<<dim3(24, 16), 256>>>(hidden, wq, wk, wv, qp, kp, vp);

    // 2) RoPE on q and k (single launch)
    rope_kernel<<<((NROWSQ + NROWSK) * 32) / 256, 256>>>(qp, kp, cosb, sinb);

    // 3) sumpass: row sums via Q.K recompute -> inv (no attn traffic)
    sumpass_kernel<<<dim3(16, BB * NH), 256, SP_SMEM>>>(qp, kp, mask, ip);

    // 4) scores: write final normalized attention (single attn write)
    scores_kernel<<<dim3(16, 16, BB * NH), 256>>>(qp, kp, mask, ip, attnp);

    // 5) ctx = P @ V (read-only attn)
    ctx_kernel<<<dim3(16, BB * NH), 256, CTX_SMEM>>>(attnp, vp, cp);

    // 6) out = ctx @ wo
    gemm_kernel<<<dim3(16, 16), 256>>>(cp, wo, outp, 2048, 2048, 2048);
}

// round 13
// speedup vs baseline: 1.4707x; 1.4707x over previous
#include <cuda_runtime.h>
#include <cuda_fp16.h>
#include <math.h>

// Problem constants
#define BB 2
#define SS 1024
#define HID 2048
#define NH 32
#define NKV 8
#define HD 64

#define OUT_ELEMS   (BB * SS * HID)             // 4,194,304
#define ATTN_ELEMS  ((size_t)BB * NH * SS * SS) // 67,108,864
#define NROWS       (BB * NH * SS)              // 65,536
#define NKT         16

// Scratch (device globals: no runtime allocation allowed)
__device__ __half g_hidh[(size_t)BB * SS * HID];
__device__ __half g_wqt[(size_t)2048 * 2048];   // [n][k] transposed
__device__ __half g_wkt[(size_t)512 * 2048];
__device__ __half g_wvt[(size_t)512 * 2048];
__device__ __half g_wot[(size_t)2048 * 2048];
__device__ __half g_qh[(size_t)BB * NH * SS * HD];
__device__ __half g_kh[(size_t)BB * NKV * SS * HD];
__device__ float  g_v[(size_t)BB * NKV * SS * HD];
__device__ __half g_ctxh[(size_t)BB * SS * HID];
__device__ float  g_part[(size_t)NROWS * NKT];
__device__ float  g_inv[NROWS];
__device__ float  g_attn_fallback[ATTN_ELEMS];

// ---------------------------------------------------------------------------
// Helpers
// ---------------------------------------------------------------------------
__device__ __forceinline__ unsigned f2tf(float f) {
    unsigned u;
    asm("cvt.rna.tf32.f32 %0, %1;" : "=r"(u) : "f"(f));
    return u;
}

__device__ __forceinline__ void mma_tf32(float c[4],
                                         unsigned a0, unsigned a1, unsigned a2, unsigned a3,
                                         unsigned b0, unsigned b1)
{
    asm volatile(
        "mma.sync.aligned.m16n8k8.row.col.f32.tf32.tf32.f32 "
        "{%0,%1,%2,%3},{%4,%5,%6,%7},{%8,%9},{%0,%1,%2,%3};"
        : "+f"(c[0]), "+f"(c[1]), "+f"(c[2]), "+f"(c[3])
        : "r"(a0), "r"(a1), "r"(a2), "r"(a3), "r"(b0), "r"(b1));
}

__device__ __forceinline__ void mma_f16(float c[4],
                                        unsigned a0, unsigned a1, unsigned a2, unsigned a3,
                                        unsigned b0, unsigned b1)
{
    asm volatile(
        "mma.sync.aligned.m16n8k16.row.col.f32.f16.f16.f32 "
        "{%0,%1,%2,%3},{%4,%5,%6,%7},{%8,%9},{%0,%1,%2,%3};"
        : "+f"(c[0]), "+f"(c[1]), "+f"(c[2]), "+f"(c[3])
        : "r"(a0), "r"(a1), "r"(a2), "r"(a3), "r"(b0), "r"(b1));
}

__device__ __forceinline__ void cpa16(void* s, const void* g) {
    unsigned sa = (unsigned)__cvta_generic_to_shared(s);
    asm volatile("cp.async.cg.shared.global [%0], [%1], 16;" :: "r"(sa), "l"(g));
}

// ---------------------------------------------------------------------------
// Conversions: hidden fp32->half (same layout); weights fp32 [K][N] ->
// half [N][K] (tiled transpose).
// ---------------------------------------------------------------------------
__global__ void convh_kernel(const float* __restrict__ in, __half* __restrict__ out)
{
    int i = blockIdx.x * blockDim.x + threadIdx.x;   // one float4
    float4 v = ((const float4*)in)[i];
    __half2* o = (__half2*)out;
    o[2 * i]     = __floats2half2_rn(v.x, v.y);
    o[2 * i + 1] = __floats2half2_rn(v.z, v.w);
}

__global__ void convt_kernel(const float* __restrict__ wq, const float* __restrict__ wk,
                             const float* __restrict__ wv, const float* __restrict__ wo,
                             __half* __restrict__ wqt, __half* __restrict__ wkt,
                             __half* __restrict__ wvt, __half* __restrict__ wot)
{
    __shared__ float tile[32][33];
    const float* src; __half* dst; int N;
    int zz = blockIdx.z;
    if (zz == 0)      { src = wq; dst = wqt; N = 2048; }
    else if (zz == 1) { src = wk; dst = wkt; N = 512;  }
    else if (zz == 2) { src = wv; dst = wvt; N = 512;  }
    else              { src = wo; dst = wot; N = 2048; }
    int n0 = blockIdx.x * 32;
    if (n0 >= N) return;
    int k0 = blockIdx.y * 32;
    for (int r = threadIdx.y; r < 32; r += 8)
        tile[r][threadIdx.x] = src[(size_t)(k0 + r) * N + n0 + threadIdx.x];
    __syncthreads();
    for (int r = threadIdx.y; r < 32; r += 8)
        dst[(size_t)(n0 + r) * 2048 + k0 + threadIdx.x] =
            __float2half_rn(tile[threadIdx.x][r]);
}

// ---------------------------------------------------------------------------
// FP16 GEMM mainloop: 128x128 tile, BK=32 halves, 3-stage cp.async ring.
// A half [M][2048] k-contig; B half [N][2048] k-contig (pre-transposed).
// Smem rows: 16 data words (32 halves) + 4 pad -> HST=20 (==4 mod 32,
// conflict-free fragment LDS). K fixed at 2048.
// ---------------------------------------------------------------------------
#define HST 20
#define HGEMM_SMEM (2 * 3 * 128 * HST * 4)   // 61440 B

__device__ __forceinline__ void hgemm_mainloop(const __half* __restrict__ Ab,
                                               const __half* __restrict__ Wb,
                                               float acc[4][4][4],
                                               unsigned* As, unsigned* Bs)
{
    const int tid = threadIdx.x;
    const int warp = tid >> 5, lane = tid & 31;
    const int g = lane >> 2, t = lane & 3;
    const int wm = warp >> 2, wn = warp & 3;
    const int ntiles = 2048 / 32;

#pragma unroll
    for (int s = 0; s < 2; s++) {
        const int k0 = s * 32;
        unsigned* An = As + s * 128 * HST;
        unsigned* Bn = Bs + s * 128 * HST;
#pragma unroll
        for (int l = 0; l < 2; l++) {
            int idx = tid + l * 256;
            int row = idx >> 2, seg = idx & 3;
            cpa16(&An[row * HST + seg * 4], Ab + (size_t)row * 2048 + k0 + seg * 8);
            cpa16(&Bn[row * HST + seg * 4], Wb + (size_t)row * 2048 + k0 + seg * 8);
        }
        asm volatile("cp.async.commit_group;");
    }

    for (int i = 0; i < ntiles; i++) {
        if (i + 2 < ntiles) {
            const int k0 = (i + 2) * 32;
            unsigned* An = As + ((i + 2) % 3) * 128 * HST;
            unsigned* Bn = Bs + ((i + 2) % 3) * 128 * HST;
#pragma unroll
            for (int l = 0; l < 2; l++) {
                int idx = tid + l * 256;
                int row = idx >> 2, seg = idx & 3;
                cpa16(&An[row * HST + seg * 4], Ab + (size_t)row * 2048 + k0 + seg * 8);
                cpa16(&Bn[row * HST + seg * 4], Wb + (size_t)row * 2048 + k0 + seg * 8);
            }
            asm volatile("cp.async.commit_group;");
            asm volatile("cp.async.wait_group 2;");
        } else if (i + 1 < ntiles) {
            asm volatile("cp.async.wait_group 1;");
        } else {
            asm volatile("cp.async.wait_group 0;");
        }
        __syncthreads();

        const unsigned* Ac = As + (i % 3) * 128 * HST;
        const unsigned* Bc = Bs + (i % 3) * 128 * HST;

#pragma unroll
        for (int kb = 0; kb < 2; kb++) {
            const int ko = kb * 8;
            unsigned a[4][4], b[4][2];
#pragma unroll
            for (int mt = 0; mt < 4; mt++) {
                int rb = wm * 64 + mt * 16;
                a[mt][0] = Ac[(rb + g) * HST + t + ko];
                a[mt][1] = Ac[(rb + g + 8) * HST + t + ko];
                a[mt][2] = Ac[(rb + g) * HST + t + 4 + ko];
                a[mt][3] = Ac[(rb + g + 8) * HST + t + 4 + ko];
            }
#pragma unroll
            for (int nt = 0; nt < 4; nt++) {
                int cb = wn * 32 + nt * 8;
                b[nt][0] = Bc[(cb + g) * HST + t + ko];
                b[nt][1] = Bc[(cb + g) * HST + t + 4 + ko];
            }
#pragma unroll
            for (int mt = 0; mt < 4; mt++)
#pragma unroll
                for (int nt = 0; nt < 4; nt++)
                    mma_f16(acc[mt][nt], a[mt][0], a[mt][1], a[mt][2], a[mt][3],
                            b[nt][0], b[nt][1]);
        }
        __syncthreads();
    }
}

// ---------------------------------------------------------------------------
// Fused QKV projection (fp16): grid (24, 16). q,k -> half; v -> fp32.
// ---------------------------------------------------------------------------
__global__ __launch_bounds__(256, 2)
void qkv_kernel(const __half* __restrict__ hid,
                const __half* __restrict__ wqt, const __half* __restrict__ wkt,
                const __half* __restrict__ wvt,
                __half* __restrict__ qo, __half* __restrict__ ko,
                float* __restrict__ vo)
{
    extern __shared__ unsigned hsm[];
    unsigned* As = hsm;
    unsigned* Bs = hsm + 3 * 128 * HST;

    const int bn = blockIdx.x, bm = blockIdx.y;
    const __half* W; int nh, bl, outk;
    if (bn < 16)      { W = wqt; nh = NH;  bl = bn;      outk = 0; }
    else if (bn < 20) { W = wkt; nh = NKV; bl = bn - 16; outk = 1; }
    else              { W = wvt; nh = NKV; bl = bn - 20; outk = 2; }

    const __half* Ab = hid + (size_t)bm * 128 * 2048;
    const __half* Wb = W + (size_t)bl * 128 * 2048;

    float acc[4][4][4];
#pragma unroll
    for (int i = 0; i < 4; i++)
#pragma unroll
        for (int j = 0; j < 4; j++)
#pragma unroll
            for (int r = 0; r < 4; r++) acc[i][j][r] = 0.f;

    hgemm_mainloop(Ab, Wb, acc, As, Bs);

    const int tid = threadIdx.x;
    const int warp = tid >> 5, lane = tid & 31;
    const int g = lane >> 2, t = lane & 3;
    const int wm = warp >> 2, wn = warp & 3;

#pragma unroll
    for (int mt = 0; mt < 4; mt++)
#pragma unroll
        for (int nt = 0; nt < 4; nt++)
#pragma unroll
            for (int ri = 0; ri < 4; ri++) {
                int r = wm * 64 + mt * 16 + g + ((ri >= 2) ? 8 : 0);
                int c = wn * 32 + nt * 8 + 2 * t + (ri & 1);
                int m = bm * 128 + r, n = bl * 128 + c;
                int b_ = m >> 10, s = m & 1023;
                int head = n >> 6, dd = n & 63;
                size_t addr = (((size_t)b_ * nh + head) * SS + s) * HD + dd;
                float v = acc[mt][nt][ri];
                if (outk == 0)      qo[addr] = __float2half_rn(v);
                else if (outk == 1) ko[addr] = __float2half_rn(v);
                else                vo[addr] = v;
            }
}

// ---------------------------------------------------------------------------
// Out projection (fp16): out[m][n] = ctxh @ wot.
// ---------------------------------------------------------------------------
__global__ __launch_bounds__(256, 2)
void gemm_kernel(const __half* __restrict__ A, const __half* __restrict__ W,
                 float* __restrict__ C)
{
    extern __shared__ unsigned hsm[];
    unsigned* As = hsm;
    unsigned* Bs = hsm + 3 * 128 * HST;

    const int bn = blockIdx.x, bm = blockIdx.y;
    const __half* Ab = A + (size_t)bm * 128 * 2048;
    const __half* Wb = W + (size_t)bn * 128 * 2048;

    float acc[4][4][4];
#pragma unroll
    for (int i = 0; i < 4; i++)
#pragma unroll
        for (int j = 0; j < 4; j++)
#pragma unroll
            for (int r = 0; r < 4; r++) acc[i][j][r] = 0.f;

    hgemm_mainloop(Ab, Wb, acc, As, Bs);

    const int tid = threadIdx.x;
    const int warp = tid >> 5, lane = tid & 31;
    const int g = lane >> 2, t = lane & 3;
    const int wm = warp >> 2, wn = warp & 3;

#pragma unroll
    for (int mt = 0; mt < 4; mt++)
#pragma unroll
        for (int nt = 0; nt < 4; nt++)
#pragma unroll
            for (int ri = 0; ri < 4; ri++) {
                int r = wm * 64 + mt * 16 + g + ((ri >= 2) ? 8 : 0);
                int c = wn * 32 + nt * 8 + 2 * t + (ri & 1);
                int m = bm * 128 + r, n = bn * 128 + c;
                C[(size_t)m * 2048 + n] = acc[mt][nt][ri];
            }
}

// ---------------------------------------------------------------------------
// RoPE on half q,k buffers (fp32 math inside).
// ---------------------------------------------------------------------------
#define NROWSQ (BB * NH * SS)
#define NROWSK (BB * NKV * SS)

__global__ void rope_kernel(__half* __restrict__ qb, __half* __restrict__ kb,
                            const float* __restrict__ cosb,
                            const float* __restrict__ sinb)
{
    int idx = blockIdx.x * blockDim.x + threadIdx.x;
    int row = idx >> 5;
    int d = idx & 31;
    __half* buf; int r;
    if (row < NROWSQ) { buf = qb; r = row; }
    else              { buf = kb; r = row - NROWSQ; }
    int s = r & (SS - 1);
    float x1 = __half2float(buf[(size_t)r * HD + d]);
    float x2 = __half2float(buf[(size_t)r * HD + d + 32]);
    float c1 = cosb[s * HD + d],      s1 = sinb[s * HD + d];
    float c2 = cosb[s * HD + d + 32], s2 = sinb[s * HD + d + 32];
    buf[(size_t)r * HD + d]      = __float2half_rn(x1 * c1 - x2 * s1);
    buf[(size_t)r * HD + d + 32] = __float2half_rn(x2 * c2 + x1 * s2);
}

// ---------------------------------------------------------------------------
// Scores (fp16): e = exp((Q.K)/8) masked -> raw e to attn + partial sums.
// Q,K half tiles cp.async'd directly; SST=36 words (==4 mod 32).
// Dead Q/K smem reused to stage e for coalesced float4 stores.
// ---------------------------------------------------------------------------
#define SST 36
#define EST 68

__global__ __launch_bounds__(256)
void scores_kernel(const __half* __restrict__ q, const __half* __restrict__ k,
                   const float* __restrict__ mask, float* __restrict__ attn,
                   float* __restrict__ part)
{
    __shared__ __align__(16) unsigned QK[2 * 64 * SST];   // 18432 B
    unsigned* Qs = QK;
    unsigned* Ks = QK + 64 * SST;

    const int kt = blockIdx.x, qt = blockIdx.y, z = blockIdx.z;
    const int b = z >> 5, h = z & 31, kvh = h >> 2;
    const int tid = threadIdx.x;
    float* outp = attn + ((size_t)z * SS + qt * 64) * SS + kt * 64;

    if (kt > qt) { // fully masked tile
        float4 zero = make_float4(0.f, 0.f, 0.f, 0.f);
#pragma unroll
        for (int i = 0; i < 4; i++) {
            int idx = tid + i * 256;
            int r = idx >> 4, c = (idx & 15) * 4;
            *(float4*)(outp + (size_t)r * SS + c) = zero;
        }
        return;
    }

    const __half* Q  = q + ((size_t)z * SS + qt * 64) * HD;
    const __half* Kp = k + ((size_t)(b * NKV + kvh) * SS + kt * 64) * HD;

    // cp.async both half tiles (64 x 64 halves each)
#pragma unroll
    for (int l = 0; l < 4; l++) {
        int idx = tid + l * 256;            // 0..1023
        int isK = idx >> 9;
        int r = (idx >> 3) & 63, seg = idx & 7;
        const __half* src = (isK ? Kp : Q) + (size_t)r * HD + seg * 8;
        unsigned* dstb = isK ? Ks : Qs;
        cpa16(&dstb[r * SST + seg * 4], src);
    }
    asm volatile("cp.async.commit_group;");
    asm volatile("cp.async.wait_group 0;");
    __syncthreads();

    const int warp = tid >> 5, lane = tid & 31;
    const int g = lane >> 2, t = lane & 3;
    const int wm = warp >> 2, wn = warp & 3;

    float acc[2][2][4];
#pragma unroll
    for (int i = 0; i < 2; i++)
#pragma unroll
        for (int j = 0; j < 2; j++)
#pragma unroll
            for (int r = 0; r < 4; r++) acc[i][j][r] = 0.f;

#pragma unroll
    for (int kb = 0; kb < 4; kb++) {
        const int ko = kb * 8;
        unsigned a[2][4], bf[2][2];
#pragma unroll
        for (int mt = 0; mt < 2; mt++) {
            int rb = wm * 32 + mt * 16;
            a[mt][0] = Qs[(rb + g) * SST + t + ko];
            a[mt][1] = Qs[(rb + g + 8) * SST + t + ko];
            a[mt][2] = Qs[(rb + g) * SST + t + 4 + ko];
            a[mt][3] = Qs[(rb + g + 8) * SST + t + 4 + ko];
        }
#pragma unroll
        for (int nt = 0; nt < 2; nt++) {
            int cb = wn * 16 + nt * 8;
            bf[nt][0] = Ks[(cb + g) * SST + t + ko];
            bf[nt][1] = Ks[(cb + g) * SST + t + 4 + ko];
        }
#pragma unroll
        for (int mt = 0; mt < 2; mt++)
#pragma unroll
            for (int nt = 0; nt < 2; nt++)
                mma_f16(acc[mt][nt], a[mt][0], a[mt][1], a[mt][2], a[mt][3],
                        bf[nt][0], bf[nt][1]);
    }
    __syncthreads();                 // all warps done reading Qs/Ks

    // ---- stage e into dead smem ----
    float* Es = (float*)QK;          // 64 x EST floats = 17408 B <= 18432
#pragma unroll
    for (int mt = 0; mt < 2; mt++)
#pragma unroll
        for (int nt = 0; nt < 2; nt++)
#pragma unroll
            for (int ri = 0; ri < 4; ri++) {
                int r = wm * 32 + mt * 16 + g + ((ri >= 2) ? 8 : 0);
                int c = wn * 16 + nt * 8 + 2 * t + (ri & 1);
                int qg = qt * 64 + r, kg = kt * 64 + c;
                bool ok = (kg <= qg) && (mask[b * SS + kg] == 1.0f);
                Es[r * EST + c] = ok ? __expf(acc[mt][nt][ri] * 0.125f) : 0.f;
            }
    __syncthreads();

    // ---- coalesced float4 store + per-row partial sum (4 threads/row) ----
    {
        const int srow = tid >> 2, q4 = tid & 3;
        const float* src = Es + srow * EST;
        float* dst = outp + (size_t)srow * SS;
        float s = 0.f;
#pragma unroll
        for (int p = 0; p < 4; p++) {
            int ch = q4 + p * 4;
            float4 e4 = *(const float4*)&src[ch * 4];
            s += e4.x + e4.y + e4.z + e4.w;
            *(float4*)(dst + ch * 4) = e4;
        }
        s += __shfl_xor_sync(0xffffffffu, s, 1);
        s += __shfl_xor_sync(0xffffffffu, s, 2);
        if (q4 == 0)
            part[((size_t)z * SS + qt * 64 + srow) * NKT + kt] = s;
    }
}

// ---------------------------------------------------------------------------
// Combine partial sums -> 1/rowsum.
// ---------------------------------------------------------------------------
__global__ void combine_kernel(const float* __restrict__ part,
                               float* __restrict__ inv)
{
    int row = blockIdx.x * blockDim.x + threadIdx.x;
    if (row >= NROWS) return;
    int qt = (row & (SS - 1)) >> 6;
    float s = 0.f;
    for (int kt = 0; kt <= qt; kt++) s += part[(size_t)row * NKT + kt];
    inv[row] = 1.0f / s;
}

// ---------------------------------------------------------------------------
// ctx (R9-proven tf32): cp.async P/V double-buffer; streams normalized attn
// (only required write); mma on raw e via cvt.rna; epilogue writes HALF ctx.
// ---------------------------------------------------------------------------
#define PST3 68
#define VST3 72
#define CTX_SMEM ((2 * 64 * PST3 + 2 * 64 * VST3 + 64) * 4)

__global__ __launch_bounds__(256)
void ctx_kernel(float* __restrict__ attn, const float* __restrict__ v,
                const float* __restrict__ inv, __half* __restrict__ ctxh)
{
    extern __shared__ float sm[];
    float* Psm  = sm;
    float* Vsm  = sm + 2 * 64 * PST3;
    float* invs = Vsm + 2 * 64 * VST3;

    const int qt = 15 - blockIdx.x;
    const int z  = blockIdx.y;
    const int b = z >> 5, h = z & 31, kvh = h >> 2;
    const int tid = threadIdx.x;
    const int warp = tid >> 5, lane = tid & 31;
    const int g = lane >> 2, t = lane & 3;
    const int wm = warp >> 2, wn = warp & 3;

    float* P = attn + ((size_t)z * SS + qt * 64) * SS;
    const float* V = v + (size_t)(b * NKV + kvh) * SS * HD;
    const int nkt = qt + 1;

    if (tid < 64) invs[tid] = inv[(size_t)z * SS + qt * 64 + tid];

    {
#pragma unroll
        for (int l = 0; l < 4; l++) {
            int i4 = tid + l * 256;
            int row = i4 >> 4, c4 = (i4 & 15) * 4;
            cpa16(&Psm[row * PST3 + c4], P + (size_t)row * SS + c4);
            cpa16(&Vsm[row * VST3 + c4], V + (size_t)row * HD + c4);
        }
        asm volatile("cp.async.commit_group;");
    }

    float acc[2][2][4];
#pragma unroll
    for (int i = 0; i < 2; i++)
#pragma unroll
        for (int j = 0; j < 2; j++)
#pragma unroll
            for (int r = 0; r < 4; r++) acc[i][j][r] = 0.f;

    for (int kt = 0; kt < nkt; kt++) {
        if (kt + 1 < nkt) {
            float* Pn = Psm + ((kt + 1) & 1) * 64 * PST3;
            float* Vn = Vsm + ((kt + 1) & 1) * 64 * VST3;
            const float* Pg = P + (size_t)(kt + 1) * 64;
            const float* Vg = V + (size_t)(kt + 1) * 64 * HD;
#pragma unroll
            for (int l = 0; l < 4; l++) {
                int i4 = tid + l * 256;
                int row = i4 >> 4, c4 = (i4 & 15) * 4;
                cpa16(&Pn[row * PST3 + c4], Pg + (size_t)row * SS + c4);
                cpa16(&Vn[row * VST3 + c4], Vg + (size_t)row * HD + c4);
            }
            asm volatile("cp.async.commit_group;");
            asm volatile("cp.async.wait_group 1;");
        } else {
            asm volatile("cp.async.wait_group 0;");
        }
        __syncthreads();

        const float* Pc = Psm + (kt & 1) * 64 * PST3;
        const float* Vc = Vsm + (kt & 1) * 64 * VST3;

        // stream normalized attention to gmem (single required write)
#pragma unroll
        for (int l = 0; l < 4; l++) {
            int i4 = tid + l * 256;
            int row = i4 >> 4, c4 = (i4 & 15) * 4;
            float iv = invs[row];
            float4 pv = *(const float4*)&Pc[row * PST3 + c4];
            pv.x *= iv; pv.y *= iv; pv.z *= iv; pv.w *= iv;
            *(float4*)(P + (size_t)row * SS + kt * 64 + c4) = pv;
        }

        // ctx += e_tile . V_tile (raw e via cvt.rna; inv at epilogue)
#pragma unroll
        for (int kb = 0; kb < 64; kb += 8) {
            unsigned a[2][4], bf[2][2];
#pragma unroll
            for (int mt = 0; mt < 2; mt++) {
                int rb = wm * 32 + mt * 16;
                a[mt][0] = f2tf(Pc[(rb + g) * PST3 + kb + t]);
                a[mt][1] = f2tf(Pc[(rb + g + 8) * PST3 + kb + t]);
                a[mt][2] = f2tf(Pc[(rb + g) * PST3 + kb + t + 4]);
                a[mt][3] = f2tf(Pc[(rb + g + 8) * PST3 + kb + t + 4]);
            }
#pragma unroll
            for (int nt = 0; nt < 2; nt++) {
                int cb = wn * 16 + nt * 8;
                bf[nt][0] = f2tf(Vc[(kb + t) * VST3 + cb + g]);
                bf[nt][1] = f2tf(Vc[(kb + t + 4) * VST3 + cb + g]);
            }
#pragma unroll
            for (int mt = 0; mt < 2; mt++)
#pragma unroll
                for (int nt = 0; nt < 2; nt++)
                    mma_tf32(acc[mt][nt], a[mt][0], a[mt][1], a[mt][2], a[mt][3],
                             bf[nt][0], bf[nt][1]);
        }
        __syncthreads();
    }

#pragma unroll
    for (int mt = 0; mt < 2; mt++)
#pragma unroll
        for (int nt = 0; nt < 2; nt++)
#pragma unroll
            for (int ri = 0; ri < 4; ri++) {
                int r = wm * 32 + mt * 16 + g + ((ri >= 2) ? 8 : 0);
                int c = wn * 16 + nt * 8 + 2 * t + (ri & 1);
                int qg = qt * 64 + r;
                ctxh[((size_t)b * SS + qg) * HID + h * HD + c] =
                    __float2half_rn(acc[mt][nt][ri] * invs[r]);
            }
}

// ---------------------------------------------------------------------------
extern "C" void kernel_launch(void* const* d_in, const int* in_sizes, int n_in,
                              void* d_out, int out_size)
{
    const float* hidden = (const float*)d_in[0];
    const float* mask   = (const float*)d_in[1];
    const float* cosb   = (const float*)d_in[2];
    const float* sinb   = (const float*)d_in[3];
    const float* wq     = (const float*)d_in[4];
    const float* wk     = (const float*)d_in[5];
    const float* wv     = (const float*)d_in[6];
    const float* wo     = (const float*)d_in[7];

    float* outp = (float*)d_out;

    __half *hidh, *wqt, *wkt, *wvt, *wot, *qh, *kh, *ctxh;
    float *vp, *pp, *ip;
    cudaGetSymbolAddress((void**)&hidh, g_hidh);
    cudaGetSymbolAddress((void**)&wqt, g_wqt);
    cudaGetSymbolAddress((void**)&wkt, g_wkt);
    cudaGetSymbolAddress((void**)&wvt, g_wvt);
    cudaGetSymbolAddress((void**)&wot, g_wot);
    cudaGetSymbolAddress((void**)&qh, g_qh);
    cudaGetSymbolAddress((void**)&kh, g_kh);
    cudaGetSymbolAddress((void**)&ctxh, g_ctxh);
    cudaGetSymbolAddress((void**)&vp, g_v);
    cudaGetSymbolAddress((void**)&pp, g_part);
    cudaGetSymbolAddress((void**)&ip, g_inv);

    float* attnp;
    if ((size_t)out_size >= OUT_ELEMS + ATTN_ELEMS) {
        attnp = outp + OUT_ELEMS;
    } else {
        cudaGetSymbolAddress((void**)&attnp, g_attn_fallback);
    }

    cudaFuncSetAttribute(qkv_kernel,
                         cudaFuncAttributeMaxDynamicSharedMemorySize, HGEMM_SMEM);
    cudaFuncSetAttribute(gemm_kernel,
                         cudaFuncAttributeMaxDynamicSharedMemorySize, HGEMM_SMEM);
    cudaFuncSetAttribute(ctx_kernel,
                         cudaFuncAttributeMaxDynamicSharedMemorySize, CTX_SMEM);

    // 0) conversions: hidden -> half; weights -> half transposed [n][k]
    convh_kernel<<<(BB * SS * HID / 4) / 256, 256>>>(hidden, hidh);
    convt_kernel<<<dim3(64, 64, 4), dim3(32, 8)>>>(wq, wk, wv, wo,
                                                   wqt, wkt, wvt, wot);

    // 1) fused QKV projection (fp16 tensor cores)
    qkv_kernel<<<dim3(24, 16), 256, HGEMM_SMEM>>>(hidh, wqt, wkt, wvt,
                                                  qh, kh, vp);

    // 2) RoPE on half q,k
    rope_kernel<<<((NROWSQ + NROWSK) * 32) / 256, 256>>>(qh, kh, cosb, sinb);

    // 3) scores (fp16) -> raw e + partial sums
    scores_kernel<<<dim3(16, 16, BB * NH), 256>>>(qh, kh, mask, attnp, pp);

    // 4) combine partials -> 1/rowsum
    combine_kernel<<<NROWS / 256, 256>>>(pp, ip);

    // 5) ctx: normalize+write attn, P@V, half ctx out
    ctx_kernel<<<dim3(16, BB * NH), 256, CTX_SMEM>>>(attnp, vp, ip, ctxh);

    // 6) out = ctxh @ wot (fp16)
    gemm_kernel<<<dim3(16, 16), 256, HGEMM_SMEM>>>(ctxh, wot, outp);
}

// round 15
// speedup vs baseline: 1.5188x; 1.0327x over previous
#include <cuda_runtime.h>
#include <cuda_fp16.h>
#include <math.h>

// Problem constants
#define BB 2
#define SS 1024
#define HID 2048
#define NH 32
#define NKV 8
#define HD 64

#define OUT_ELEMS   (BB * SS * HID)             // 4,194,304
#define ATTN_ELEMS  ((size_t)BB * NH * SS * SS) // 67,108,864
#define NROWS       (BB * NH * SS)              // 65,536
#define NKT         16

// Scratch (device globals: no runtime allocation allowed)
__device__ __half g_hidh[(size_t)BB * SS * HID];
__device__ __half g_wqt[(size_t)2048 * 2048];   // [n][k] transposed
__device__ __half g_wkt[(size_t)512 * 2048];
__device__ __half g_wvt[(size_t)512 * 2048];
__device__ __half g_wot[(size_t)2048 * 2048];
__device__ __half g_qh[(size_t)BB * NH * SS * HD];
__device__ __half g_kh[(size_t)BB * NKV * SS * HD];
__device__ __half g_vth[(size_t)BB * NKV * HD * SS];   // V^T: [b,kv][d][s]
__device__ __half g_ctxh[(size_t)BB * SS * HID];
__device__ float  g_part[(size_t)NROWS * NKT];
__device__ float  g_inv[NROWS];
__device__ float  g_attn_fallback[ATTN_ELEMS];

// ---------------------------------------------------------------------------
// Helpers
// ---------------------------------------------------------------------------
__device__ __forceinline__ unsigned h2u(__half2 h) {
    unsigned u;
    memcpy(&u, &h, 4);
    return u;
}

__device__ __forceinline__ void mma_f16(float c[4],
                                        unsigned a0, unsigned a1, unsigned a2, unsigned a3,
                                        unsigned b0, unsigned b1)
{
    asm volatile(
        "mma.sync.aligned.m16n8k16.row.col.f32.f16.f16.f32 "
        "{%0,%1,%2,%3},{%4,%5,%6,%7},{%8,%9},{%0,%1,%2,%3};"
        : "+f"(c[0]), "+f"(c[1]), "+f"(c[2]), "+f"(c[3])
        : "r"(a0), "r"(a1), "r"(a2), "r"(a3), "r"(b0), "r"(b1));
}

__device__ __forceinline__ void cpa16(void* s, const void* g) {
    unsigned sa = (unsigned)__cvta_generic_to_shared(s);
    asm volatile("cp.async.cg.shared.global [%0], [%1], 16;" :: "r"(sa), "l"(g));
}

// ---------------------------------------------------------------------------
// Conversions: hidden fp32->half; weights fp32 [K][N] -> half [N][K].
// ---------------------------------------------------------------------------
__global__ void convh_kernel(const float* __restrict__ in, __half* __restrict__ out)
{
    int i = blockIdx.x * blockDim.x + threadIdx.x;   // one float4
    float4 v = ((const float4*)in)[i];
    __half2* o = (__half2*)out;
    o[2 * i]     = __floats2half2_rn(v.x, v.y);
    o[2 * i + 1] = __floats2half2_rn(v.z, v.w);
}

__global__ void convt_kernel(const float* __restrict__ wq, const float* __restrict__ wk,
                             const float* __restrict__ wv, const float* __restrict__ wo,
                             __half* __restrict__ wqt, __half* __restrict__ wkt,
                             __half* __restrict__ wvt, __half* __restrict__ wot)
{
    __shared__ float tile[32][33];
    const float* src; __half* dst; int N;
    int zz = blockIdx.z;
    if (zz == 0)      { src = wq; dst = wqt; N = 2048; }
    else if (zz == 1) { src = wk; dst = wkt; N = 512;  }
    else if (zz == 2) { src = wv; dst = wvt; N = 512;  }
    else              { src = wo; dst = wot; N = 2048; }
    int n0 = blockIdx.x * 32;
    if (n0 >= N) return;
    int k0 = blockIdx.y * 32;
    for (int r = threadIdx.y; r < 32; r += 8)
        tile[r][threadIdx.x] = src[(size_t)(k0 + r) * N + n0 + threadIdx.x];
    __syncthreads();
    for (int r = threadIdx.y; r < 32; r += 8)
        dst[(size_t)(n0 + r) * 2048 + k0 + threadIdx.x] =
            __float2half_rn(tile[threadIdx.x][r]);
}

// ---------------------------------------------------------------------------
// FP16 GEMM mainloop: 128x128 tile, BK=32 halves, 3-stage cp.async ring.
// ---------------------------------------------------------------------------
#define HST 20
#define HGEMM_SMEM (2 * 3 * 128 * HST * 4)   // 61440 B

__device__ __forceinline__ void hgemm_mainloop(const __half* __restrict__ Ab,
                                               const __half* __restrict__ Wb,
                                               float acc[4][4][4],
                                               unsigned* As, unsigned* Bs)
{
    const int tid = threadIdx.x;
    const int warp = tid >> 5, lane = tid & 31;
    const int g = lane >> 2, t = lane & 3;
    const int wm = warp >> 2, wn = warp & 3;
    const int ntiles = 2048 / 32;

#pragma unroll
    for (int s = 0; s < 2; s++) {
        const int k0 = s * 32;
        unsigned* An = As + s * 128 * HST;
        unsigned* Bn = Bs + s * 128 * HST;
#pragma unroll
        for (int l = 0; l < 2; l++) {
            int idx = tid + l * 256;
            int row = idx >> 2, seg = idx & 3;
            cpa16(&An[row * HST + seg * 4], Ab + (size_t)row * 2048 + k0 + seg * 8);
            cpa16(&Bn[row * HST + seg * 4], Wb + (size_t)row * 2048 + k0 + seg * 8);
        }
        asm volatile("cp.async.commit_group;");
    }

    for (int i = 0; i < ntiles; i++) {
        if (i + 2 < ntiles) {
            const int k0 = (i + 2) * 32;
            unsigned* An = As + ((i + 2) % 3) * 128 * HST;
            unsigned* Bn = Bs + ((i + 2) % 3) * 128 * HST;
#pragma unroll
            for (int l = 0; l < 2; l++) {
                int idx = tid + l * 256;
                int row = idx >> 2, seg = idx & 3;
                cpa16(&An[row * HST + seg * 4], Ab + (size_t)row * 2048 + k0 + seg * 8);
                cpa16(&Bn[row * HST + seg * 4], Wb + (size_t)row * 2048 + k0 + seg * 8);
            }
            asm volatile("cp.async.commit_group;");
            asm volatile("cp.async.wait_group 2;");
        } else if (i + 1 < ntiles) {
            asm volatile("cp.async.wait_group 1;");
        } else {
            asm volatile("cp.async.wait_group 0;");
        }
        __syncthreads();

        const unsigned* Ac = As + (i % 3) * 128 * HST;
        const unsigned* Bc = Bs + (i % 3) * 128 * HST;

#pragma unroll
        for (int kb = 0; kb < 2; kb++) {
            const int ko = kb * 8;
            unsigned a[4][4], b[4][2];
#pragma unroll
            for (int mt = 0; mt < 4; mt++) {
                int rb = wm * 64 + mt * 16;
                a[mt][0] = Ac[(rb + g) * HST + t + ko];
                a[mt][1] = Ac[(rb + g + 8) * HST + t + ko];
                a[mt][2] = Ac[(rb + g) * HST + t + 4 + ko];
                a[mt][3] = Ac[(rb + g + 8) * HST + t + 4 + ko];
            }
#pragma unroll
            for (int nt = 0; nt < 4; nt++) {
                int cb = wn * 32 + nt * 8;
                b[nt][0] = Bc[(cb + g) * HST + t + ko];
                b[nt][1] = Bc[(cb + g) * HST + t + 4 + ko];
            }
#pragma unroll
            for (int mt = 0; mt < 4; mt++)
#pragma unroll
                for (int nt = 0; nt < 4; nt++)
                    mma_f16(acc[mt][nt], a[mt][0], a[mt][1], a[mt][2], a[mt][3],
                            b[nt][0], b[nt][1]);
        }
        __syncthreads();
    }
}

// ---------------------------------------------------------------------------
// Fused QKV projection (fp16): grid (24, 16). q,k -> half (b,h,s,d);
// v -> half TRANSPOSED (b,kv,d,s) for fp16 ctx B-fragments.
// ---------------------------------------------------------------------------
__global__ __launch_bounds__(256, 2)
void qkv_kernel(const __half* __restrict__ hid,
                const __half* __restrict__ wqt, const __half* __restrict__ wkt,
                const __half* __restrict__ wvt,
                __half* __restrict__ qo, __half* __restrict__ ko,
                __half* __restrict__ vto)
{
    extern __shared__ unsigned hsm[];
    unsigned* As = hsm;
    unsigned* Bs = hsm + 3 * 128 * HST;

    const int bn = blockIdx.x, bm = blockIdx.y;
    const __half* W; int bl, outk;
    if (bn < 16)      { W = wqt; bl = bn;      outk = 0; }
    else if (bn < 20) { W = wkt; bl = bn - 16; outk = 1; }
    else              { W = wvt; bl = bn - 20; outk = 2; }

    const __half* Ab = hid + (size_t)bm * 128 * 2048;
    const __half* Wb = W + (size_t)bl * 128 * 2048;

    float acc[4][4][4];
#pragma unroll
    for (int i = 0; i < 4; i++)
#pragma unroll
        for (int j = 0; j < 4; j++)
#pragma unroll
            for (int r = 0; r < 4; r++) acc[i][j][r] = 0.f;

    hgemm_mainloop(Ab, Wb, acc, As, Bs);

    const int tid = threadIdx.x;
    const int warp = tid >> 5, lane = tid & 31;
    const int g = lane >> 2, t = lane & 3;
    const int wm = warp >> 2, wn = warp & 3;

#pragma unroll
    for (int mt = 0; mt < 4; mt++)
#pragma unroll
        for (int nt = 0; nt < 4; nt++)
#pragma unroll
            for (int ri = 0; ri < 4; ri++) {
                int r = wm * 64 + mt * 16 + g + ((ri >= 2) ? 8 : 0);
                int c = wn * 32 + nt * 8 + 2 * t + (ri & 1);
                int m = bm * 128 + r, n = bl * 128 + c;
                int b_ = m >> 10, s = m & 1023;
                int head = n >> 6, dd = n & 63;
                __half hv = __float2half_rn(acc[mt][nt][ri]);
                if (outk == 0)
                    qo[(((size_t)b_ * NH + head) * SS + s) * HD + dd] = hv;
                else if (outk == 1)
                    ko[(((size_t)b_ * NKV + head) * SS + s) * HD + dd] = hv;
                else
                    vto[(((size_t)b_ * NKV + head) * HD + dd) * SS + s] = hv;
            }
}

// ---------------------------------------------------------------------------
// Out projection (fp16): out[m][n] = ctxh @ wot.
// ---------------------------------------------------------------------------
__global__ __launch_bounds__(256, 2)
void gemm_kernel(const __half* __restrict__ A, const __half* __restrict__ W,
                 float* __restrict__ C)
{
    extern __shared__ unsigned hsm[];
    unsigned* As = hsm;
    unsigned* Bs = hsm + 3 * 128 * HST;

    const int bn = blockIdx.x, bm = blockIdx.y;
    const __half* Ab = A + (size_t)bm * 128 * 2048;
    const __half* Wb = W + (size_t)bn * 128 * 2048;

    float acc[4][4][4];
#pragma unroll
    for (int i = 0; i < 4; i++)
#pragma unroll
        for (int j = 0; j < 4; j++)
#pragma unroll
            for (int r = 0; r < 4; r++) acc[i][j][r] = 0.f;

    hgemm_mainloop(Ab, Wb, acc, As, Bs);

    const int tid = threadIdx.x;
    const int warp = tid >> 5, lane = tid & 31;
    const int g = lane >> 2, t = lane & 3;
    const int wm = warp >> 2, wn = warp & 3;

#pragma unroll
    for (int mt = 0; mt < 4; mt++)
#pragma unroll
        for (int nt = 0; nt < 4; nt++)
#pragma unroll
            for (int ri = 0; ri < 4; ri++) {
                int r = wm * 64 + mt * 16 + g + ((ri >= 2) ? 8 : 0);
                int c = wn * 32 + nt * 8 + 2 * t + (ri & 1);
                int m = bm * 128 + r, n = bn * 128 + c;
                C[(size_t)m * 2048 + n] = acc[mt][nt][ri];
            }
}

// ---------------------------------------------------------------------------
// RoPE on half q,k buffers (fp32 math inside).
// ---------------------------------------------------------------------------
#define NROWSQ (BB * NH * SS)
#define NROWSK (BB * NKV * SS)

__global__ void rope_kernel(__half* __restrict__ qb, __half* __restrict__ kb,
                            const float* __restrict__ cosb,
                            const float* __restrict__ sinb)
{
    int idx = blockIdx.x * blockDim.x + threadIdx.x;
    int row = idx >> 5;
    int d = idx & 31;
    __half* buf; int r;
    if (row < NROWSQ) { buf = qb; r = row; }
    else              { buf = kb; r = row - NROWSQ; }
    int s = r & (SS - 1);
    float x1 = __half2float(buf[(size_t)r * HD + d]);
    float x2 = __half2float(buf[(size_t)r * HD + d + 32]);
    float c1 = cosb[s * HD + d],      s1 = sinb[s * HD + d];
    float c2 = cosb[s * HD + d + 32], s2 = sinb[s * HD + d + 32];
    buf[(size_t)r * HD + d]      = __float2half_rn(x1 * c1 - x2 * s1);
    buf[(size_t)r * HD + d + 32] = __float2half_rn(x2 * c2 + x1 * s2);
}

// ---------------------------------------------------------------------------
// Scores (fp16): e = exp((Q.K)/8) masked -> raw e (fp32) to attn + partials.
// ---------------------------------------------------------------------------
#define SST 36
#define EST 68

__global__ __launch_bounds__(256)
void scores_kernel(const __half* __restrict__ q, const __half* __restrict__ k,
                   const float* __restrict__ mask, float* __restrict__ attn,
                   float* __restrict__ part)
{
    __shared__ __align__(16) unsigned QK[2 * 64 * SST];   // 18432 B
    unsigned* Qs = QK;
    unsigned* Ks = QK + 64 * SST;

    const int kt = blockIdx.x, qt = blockIdx.y, z = blockIdx.z;
    const int b = z >> 5, h = z & 31, kvh = h >> 2;
    const int tid = threadIdx.x;
    float* outp = attn + ((size_t)z * SS + qt * 64) * SS + kt * 64;

    if (kt > qt) { // fully masked tile
        float4 zero = make_float4(0.f, 0.f, 0.f, 0.f);
#pragma unroll
        for (int i = 0; i < 4; i++) {
            int idx = tid + i * 256;
            int r = idx >> 4, c = (idx & 15) * 4;
            *(float4*)(outp + (size_t)r * SS + c) = zero;
        }
        return;
    }

    const __half* Q  = q + ((size_t)z * SS + qt * 64) * HD;
    const __half* Kp = k + ((size_t)(b * NKV + kvh) * SS + kt * 64) * HD;

#pragma unroll
    for (int l = 0; l < 4; l++) {
        int idx = tid + l * 256;            // 0..1023
        int isK = idx >> 9;
        int r = (idx >> 3) & 63, seg = idx & 7;
        const __half* src = (isK ? Kp : Q) + (size_t)r * HD + seg * 8;
        unsigned* dstb = isK ? Ks : Qs;
        cpa16(&dstb[r * SST + seg * 4], src);
    }
    asm volatile("cp.async.commit_group;");
    asm volatile("cp.async.wait_group 0;");
    __syncthreads();

    const int warp = tid >> 5, lane = tid & 31;
    const int g = lane >> 2, t = lane & 3;
    const int wm = warp >> 2, wn = warp & 3;

    float acc[2][2][4];
#pragma unroll
    for (int i = 0; i < 2; i++)
#pragma unroll
        for (int j = 0; j < 2; j++)
#pragma unroll
            for (int r = 0; r < 4; r++) acc[i][j][r] = 0.f;

#pragma unroll
    for (int kb = 0; kb < 4; kb++) {
        const int ko = kb * 8;
        unsigned a[2][4], bf[2][2];
#pragma unroll
        for (int mt = 0; mt < 2; mt++) {
            int rb = wm * 32 + mt * 16;
            a[mt][0] = Qs[(rb + g) * SST + t + ko];
            a[mt][1] = Qs[(rb + g + 8) * SST + t + ko];
            a[mt][2] = Qs[(rb + g) * SST + t + 4 + ko];
            a[mt][3] = Qs[(rb + g + 8) * SST + t + 4 + ko];
        }
#pragma unroll
        for (int nt = 0; nt < 2; nt++) {
            int cb = wn * 16 + nt * 8;
            bf[nt][0] = Ks[(cb + g) * SST + t + ko];
            bf[nt][1] = Ks[(cb + g) * SST + t + 4 + ko];
        }
#pragma unroll
        for (int mt = 0; mt < 2; mt++)
#pragma unroll
            for (int nt = 0; nt < 2; nt++)
                mma_f16(acc[mt][nt], a[mt][0], a[mt][1], a[mt][2], a[mt][3],
                        bf[nt][0], bf[nt][1]);
    }
    __syncthreads();

    // ---- stage e into dead smem ----
    float* Es = (float*)QK;          // 64 x EST floats = 17408 B <= 18432
#pragma unroll
    for (int mt = 0; mt < 2; mt++)
#pragma unroll
        for (int nt = 0; nt < 2; nt++)
#pragma unroll
            for (int ri = 0; ri < 4; ri++) {
                int r = wm * 32 + mt * 16 + g + ((ri >= 2) ? 8 : 0);
                int c = wn * 16 + nt * 8 + 2 * t + (ri & 1);
                int qg = qt * 64 + r, kg = kt * 64 + c;
                bool ok = (kg <= qg) && (mask[b * SS + kg] == 1.0f);
                Es[r * EST + c] = ok ? __expf(acc[mt][nt][ri] * 0.125f) : 0.f;
            }
    __syncthreads();

    // ---- coalesced float4 store + per-row partial sum (4 threads/row) ----
    {
        const int srow = tid >> 2, q4 = tid & 3;
        const float* src = Es + srow * EST;
        float* dst = outp + (size_t)srow * SS;
        float s = 0.f;
#pragma unroll
        for (int p = 0; p < 4; p++) {
            int ch = q4 + p * 4;
            float4 e4 = *(const float4*)&src[ch * 4];
            s += e4.x + e4.y + e4.z + e4.w;
            *(float4*)(dst + ch * 4) = e4;
        }
        s += __shfl_xor_sync(0xffffffffu, s, 1);
        s += __shfl_xor_sync(0xffffffffu, s, 2);
        if (q4 == 0)
            part[((size_t)z * SS + qt * 64 + srow) * NKT + kt] = s;
    }
}

// ---------------------------------------------------------------------------
// Combine partial sums -> 1/rowsum.
// ---------------------------------------------------------------------------
__global__ void combine_kernel(const float* __restrict__ part,
                               float* __restrict__ inv)
{
    int row = blockIdx.x * blockDim.x + threadIdx.x;
    if (row >= NROWS) return;
    int qt = (row & (SS - 1)) >> 6;
    float s = 0.f;
    for (int kt = 0; kt <= qt; kt++) s += part[(size_t)row * NKT + kt];
    inv[row] = 1.0f / s;
}

// ---------------------------------------------------------------------------
// ctx (fp16): cp.async fp32 P + half V^T double-buffered. Per tile:
// normalize pass writes fp32 attn (only required write) AND stores the
// normalized P as half2 into Phw; fp16 mma (P@V) with zero in-loop cvts.
// Smem ~61 KB -> 3 CTAs/SM.
// ---------------------------------------------------------------------------
#define PST3 68
#define VSW  36
#define PHW  36
#define CTX_SMEM ((2 * 64 * PST3 + 2 * 64 * VSW + 64 * PHW + 64) * 4)

__global__ __launch_bounds__(256)
void ctx_kernel(float* __restrict__ attn, const __half* __restrict__ vt,
                const float* __restrict__ inv, __half* __restrict__ ctxh)
{
    extern __shared__ float sm[];
    float*    Psm  = sm;                          // 2 x 64 x PST3 fp32
    unsigned* Vsm  = (unsigned*)(sm + 2 * 64 * PST3);  // 2 x 64 x VSW half2
    unsigned* Phw  = Vsm + 2 * 64 * VSW;          // 64 x PHW half2 (norm. P)
    float*    invs = (float*)(Phw + 64 * PHW);    // 64

    const int qt = 15 - blockIdx.x;
    const int z  = blockIdx.y;
    const int b = z >> 5, h = z & 31, kvh = h >> 2;
    const int tid = threadIdx.x;
    const int warp = tid >> 5, lane = tid & 31;
    const int g = lane >> 2, t = lane & 3;
    const int wm = warp >> 2, wn = warp & 3;

    float* P = attn + ((size_t)z * SS + qt * 64) * SS;
    const __half* V = vt + (size_t)(b * NKV + kvh) * HD * SS;   // [d][s]
    const int nkt = qt + 1;

    if (tid < 64) invs[tid] = inv[(size_t)z * SS + qt * 64 + tid];

    // prologue: tile 0 (P: 64x64 fp32; V^T: 64d x 64s half)
    {
#pragma unroll
        for (int l = 0; l < 4; l++) {
            int i4 = tid + l * 256;
            int row = i4 >> 4, c4 = (i4 & 15) * 4;
            cpa16(&Psm[row * PST3 + c4], P + (size_t)row * SS + c4);
        }
#pragma unroll
        for (int l = 0; l < 2; l++) {
            int idx = tid + l * 256;
            int d = idx >> 3, seg = idx & 7;
            cpa16(&Vsm[d * VSW + seg * 4], V + (size_t)d * SS + seg * 8);
        }
        asm volatile("cp.async.commit_group;");
    }

    float acc[2][2][4];
#pragma unroll
    for (int i = 0; i < 2; i++)
#pragma unroll
        for (int j = 0; j < 2; j++)
#pragma unroll
            for (int r = 0; r < 4; r++) acc[i][j][r] = 0.f;

    for (int kt = 0; kt < nkt; kt++) {
        if (kt + 1 < nkt) {
            float*    Pn = Psm + ((kt + 1) & 1) * 64 * PST3;
            unsigned* Vn = Vsm + ((kt + 1) & 1) * 64 * VSW;
            const float*  Pg = P + (size_t)(kt + 1) * 64;
            const __half* Vg = V + (size_t)(kt + 1) * 64;
#pragma unroll
            for (int l = 0; l < 4; l++) {
                int i4 = tid + l * 256;
                int row = i4 >> 4, c4 = (i4 & 15) * 4;
                cpa16(&Pn[row * PST3 + c4], Pg + (size_t)row * SS + c4);
            }
#pragma unroll
            for (int l = 0; l < 2; l++) {
                int idx = tid + l * 256;
                int d = idx >> 3, seg = idx & 7;
                cpa16(&Vn[d * VSW + seg * 4], Vg + (size_t)d * SS + seg * 8);
            }
            asm volatile("cp.async.commit_group;");
            asm volatile("cp.async.wait_group 1;");
        } else {
            asm volatile("cp.async.wait_group 0;");
        }
        __syncthreads();

        const float*    Pc = Psm + (kt & 1) * 64 * PST3;
        const unsigned* Vc = Vsm + (kt & 1) * 64 * VSW;

        // normalize: write fp32 attn (required) + half2 normalized P to Phw
#pragma unroll
        for (int l = 0; l < 4; l++) {
            int i4 = tid + l * 256;
            int row = i4 >> 4, c16 = (i4 & 15);
            float iv = invs[row];
            float4 pv = *(const float4*)&Pc[row * PST3 + c16 * 4];
            pv.x *= iv; pv.y *= iv; pv.z *= iv; pv.w *= iv;
            *(float4*)(P + (size_t)row * SS + kt * 64 + c16 * 4) = pv;
            Phw[row * PHW + c16 * 2]     = h2u(__floats2half2_rn(pv.x, pv.y));
            Phw[row * PHW + c16 * 2 + 1] = h2u(__floats2half2_rn(pv.z, pv.w));
        }
        __syncthreads();

        // ctx += Pn_tile . V_tile (fp16 mma, fp32 accumulate)
#pragma unroll
        for (int kb = 0; kb < 4; kb++) {
            const int ko = kb * 8;
            unsigned a[2][4], bf[2][2];
#pragma unroll
            for (int mt = 0; mt < 2; mt++) {
                int rb = wm * 32 + mt * 16;
                a[mt][0] = Phw[(rb + g) * PHW + t + ko];
                a[mt][1] = Phw[(rb + g + 8) * PHW + t + ko];
                a[mt][2] = Phw[(rb + g) * PHW + t + 4 + ko];
                a[mt][3] = Phw[(rb + g + 8) * PHW + t + 4 + ko];
            }
#pragma unroll
            for (int nt = 0; nt < 2; nt++) {
                int cb = wn * 16 + nt * 8;
                bf[nt][0] = Vc[(cb + g) * VSW + t + ko];
                bf[nt][1] = Vc[(cb + g) * VSW + t + 4 + ko];
            }
#pragma unroll
            for (int mt = 0; mt < 2; mt++)
#pragma unroll
                for (int nt = 0; nt < 2; nt++)
                    mma_f16(acc[mt][nt], a[mt][0], a[mt][1], a[mt][2], a[mt][3],
                            bf[nt][0], bf[nt][1]);
        }
        __syncthreads();
    }

#pragma unroll
    for (int mt = 0; mt < 2; mt++)
#pragma unroll
        for (int nt = 0; nt < 2; nt++)
#pragma unroll
            for (int ri = 0; ri < 4; ri++) {
                int r = wm * 32 + mt * 16 + g + ((ri >= 2) ? 8 : 0);
                int c = wn * 16 + nt * 8 + 2 * t + (ri & 1);
                int qg = qt * 64 + r;
                ctxh[((size_t)b * SS + qg) * HID + h * HD + c] =
                    __float2half_rn(acc[mt][nt][ri]);
            }
}

// ---------------------------------------------------------------------------
extern "C" void kernel_launch(void* const* d_in, const int* in_sizes, int n_in,
                              void* d_out, int out_size)
{
    const float* hidden = (const float*)d_in[0];
    const float* mask   = (const float*)d_in[1];
    const float* cosb   = (const float*)d_in[2];
    const float* sinb   = (const float*)d_in[3];
    const float* wq     = (const float*)d_in[4];
    const float* wk     = (const float*)d_in[5];
    const float* wv     = (const float*)d_in[6];
    const float* wo     = (const float*)d_in[7];

    float* outp = (float*)d_out;

    __half *hidh, *wqt, *wkt, *wvt, *wot, *qh, *kh, *vth, *ctxh;
    float *pp, *ip;
    cudaGetSymbolAddress((void**)&hidh, g_hidh);
    cudaGetSymbolAddress((void**)&wqt, g_wqt);
    cudaGetSymbolAddress((void**)&wkt, g_wkt);
    cudaGetSymbolAddress((void**)&wvt, g_wvt);
    cudaGetSymbolAddress((void**)&wot, g_wot);
    cudaGetSymbolAddress((void**)&qh, g_qh);
    cudaGetSymbolAddress((void**)&kh, g_kh);
    cudaGetSymbolAddress((void**)&vth, g_vth);
    cudaGetSymbolAddress((void**)&ctxh, g_ctxh);
    cudaGetSymbolAddress((void**)&pp, g_part);
    cudaGetSymbolAddress((void**)&ip, g_inv);

    float* attnp;
    if ((size_t)out_size >= OUT_ELEMS + ATTN_ELEMS) {
        attnp = outp + OUT_ELEMS;
    } else {
        cudaGetSymbolAddress((void**)&attnp, g_attn_fallback);
    }

    cudaFuncSetAttribute(qkv_kernel,
                         cudaFuncAttributeMaxDynamicSharedMemorySize, HGEMM_SMEM);
    cudaFuncSetAttribute(gemm_kernel,
                         cudaFuncAttributeMaxDynamicSharedMemorySize, HGEMM_SMEM);
    cudaFuncSetAttribute(ctx_kernel,
                         cudaFuncAttributeMaxDynamicSharedMemorySize, CTX_SMEM);

    // 0) conversions
    convh_kernel<<<(BB * SS * HID / 4) / 256, 256>>>(hidden, hidh);
    convt_kernel<<<dim3(64, 64, 4), dim3(32, 8)>>>(wq, wk, wv, wo,
                                                   wqt, wkt, wvt, wot);

    // 1) fused QKV projection (fp16); V stored transposed half
    qkv_kernel<<<dim3(24, 16), 256, HGEMM_SMEM>>>(hidh, wqt, wkt, wvt,
                                                  qh, kh, vth);

    // 2) RoPE on half q,k
    rope_kernel<<<((NROWSQ + NROWSK) * 32) / 256, 256>>>(qh, kh, cosb, sinb);

    // 3) scores (fp16) -> raw e + partial sums
    scores_kernel<<<dim3(16, 16, BB * NH), 256>>>(qh, kh, mask, attnp, pp);

    // 4) combine partials -> 1/rowsum
    combine_kernel<<<NROWS / 256, 256>>>(pp, ip);

    // 5) ctx (fp16): normalize+write attn, P@V^T, half ctx out
    ctx_kernel<<<dim3(16, BB * NH), 256, CTX_SMEM>>>(attnp, vth, ip, ctxh);

    // 6) out = ctxh @ wot (fp16)
    gemm_kernel<<<dim3(16, 16), 256, HGEMM_SMEM>>>(ctxh, wot, outp);
}